// round 16
// baseline (speedup 1.0000x reference)
#include <cuda_runtime.h>
#include <cuda_bf16.h>
#include <cstdint>

#define N_NODES 50000
#define N_EDGES 800000
#define F 128
#define NBLK_SCAN 196        // ceil(50000/256)

// ---------------- scratch (static device memory) -----------------------------
__device__ short g_xq[(size_t)N_NODES * F];             // int16 x
__device__ short g_hq[2][(size_t)N_NODES * F];          // int16 hidden (ping-pong)
__device__ short g_mq[(size_t)N_NODES * F];             // int16 mean
__device__ float g_sx[N_NODES];                         // row scales
__device__ float g_sh[2][N_NODES];
__device__ float g_sm[N_NODES];
__device__ __nv_bfloat16 g_whi[3 * 128 * 256];          // combined [Wl|Wr] hi
__device__ __nv_bfloat16 g_wlo[3 * 128 * 256];          // combined [Wl|Wr] lo
__device__ int g_deg[N_NODES];                          // zero-init; re-zeroed by k_final
__device__ int g_off[N_NODES];
__device__ int g_cursor[N_NODES];
__device__ int g_srcs[N_EDGES];
__device__ int g_blockagg[NBLK_SCAN];
__device__ int g_blockpref[NBLK_SCAN];
__device__ int g_aggdone;
__device__ int g_prefflag;

// ---------------- helpers ------------------------------------------------------
__device__ __forceinline__ unsigned smem_u32(const void* p) {
    unsigned a;
    asm("{ .reg .u64 t; cvta.to.shared.u64 t, %1; cvt.u32.u64 %0, t; }" : "=r"(a) : "l"(p));
    return a;
}
__device__ __forceinline__ void ldsm_x4(unsigned* r, unsigned addr) {
    asm volatile("ldmatrix.sync.aligned.m8n8.x4.shared.b16 {%0,%1,%2,%3}, [%4];"
                 : "=r"(r[0]), "=r"(r[1]), "=r"(r[2]), "=r"(r[3]) : "r"(addr));
}
__device__ __forceinline__ void mma16816(float* c, const unsigned* a, const unsigned* b) {
    asm volatile(
        "mma.sync.aligned.m16n8k16.row.col.f32.bf16.bf16.f32 "
        "{%0,%1,%2,%3}, {%4,%5,%6,%7}, {%8,%9}, {%0,%1,%2,%3};"
        : "+f"(c[0]), "+f"(c[1]), "+f"(c[2]), "+f"(c[3])
        : "r"(a[0]), "r"(a[1]), "r"(a[2]), "r"(a[3]), "r"(b[0]), "r"(b[1]));
}
__device__ __forceinline__ void split2(float f0, float f1, unsigned& hw, unsigned& lw) {
    __nv_bfloat162 hb = __floats2bfloat162_rn(f0, f1);
    hw = *(unsigned*)&hb;
    float r0 = f0 - __uint_as_float(hw << 16);
    float r1 = f1 - __uint_as_float(hw & 0xFFFF0000u);
    __nv_bfloat162 lb = __floats2bfloat162_rn(r0, r1);
    lw = *(unsigned*)&lb;
}
__device__ __forceinline__ void cp16(unsigned dst, const void* src) {
    asm volatile("cp.async.cg.shared.global [%0], [%1], 16;" :: "r"(dst), "l"(src));
}
#define CP_COMMIT() asm volatile("cp.async.commit_group;" ::: "memory")
#define CP_WAIT0()  asm volatile("cp.async.wait_group 0;" ::: "memory")

// ---------------- launch 0: prep (pack W + hist + quantize x + flags) -----------
// grid: N_NODES*32/256 = 6250 blocks
__global__ void k_prep(const float* __restrict__ x,
                       const int* __restrict__ edge,
                       const float* Wl0, const float* Wr0,
                       const float* Wl1, const float* Wr1,
                       const float* Wl2, const float* Wr2) {
    int gid = blockIdx.x * blockDim.x + threadIdx.x;
    if (gid == 0) { g_aggdone = 0; g_prefflag = 0; }
    if (gid < N_EDGES / 4) {
        uint4 d = *(const uint4*)(edge + N_EDGES + gid * 4);
        if (d.x < N_NODES) atomicAdd(&g_deg[d.x], 1);
        if (d.y < N_NODES) atomicAdd(&g_deg[d.y], 1);
        if (d.z < N_NODES) atomicAdd(&g_deg[d.z], 1);
        if (d.w < N_NODES) atomicAdd(&g_deg[d.w], 1);
    }
    if (gid < 3 * 128 * 256) {
        int L = gid / (128 * 256);
        int r = gid % (128 * 256);
        int n = r / 256;
        int k = r % 256;
        const float* Wl = (L == 0) ? Wl0 : (L == 1) ? Wl1 : Wl2;
        const float* Wr = (L == 0) ? Wr0 : (L == 1) ? Wr1 : Wr2;
        float v = (k < 128) ? Wl[n * 128 + k] : Wr[n * 128 + (k - 128)];
        __nv_bfloat16 h = __float2bfloat16(v);
        float r2 = v - __bfloat162float(h);
        g_whi[gid] = h;
        g_wlo[gid] = __float2bfloat16(r2);
    }
    // quantize x: one warp per row
    int row = gid >> 5;
    int lane = gid & 31;
    if (row < N_NODES) {
        float4 v = ((const float4*)x)[gid];
        float m = fmaxf(fmaxf(fabsf(v.x), fabsf(v.y)), fmaxf(fabsf(v.z), fabsf(v.w)));
#pragma unroll
        for (int o = 16; o > 0; o >>= 1) m = fmaxf(m, __shfl_xor_sync(0xFFFFFFFFu, m, o));
        float qs = (m > 0.f) ? 32766.f / m : 0.f;
        int q0 = __float2int_rn(v.x * qs), q1 = __float2int_rn(v.y * qs);
        int q2 = __float2int_rn(v.z * qs), q3 = __float2int_rn(v.w * qs);
        uint2 oq;
        oq.x = (q0 & 0xFFFF) | (q1 << 16);
        oq.y = (q2 & 0xFFFF) | (q3 << 16);
        ((uint2*)g_xq)[gid] = oq;
        if (lane == 0) g_sx[row] = m / 32766.f;
    }
}

// ---------------- launch 1: fused scan + scatter (grid-resident) ----------------
#define EDGES_PER_BLK 1021    // 196*1021*4 >= 800000 (units of 4 edges)
__global__ void __launch_bounds__(256, 8) k_scan_scatter(const int* __restrict__ edge) {
    __shared__ int s[256];
    __shared__ int ag[256];
    __shared__ int is_last;
    int b = blockIdx.x, t = threadIdx.x;
    int i = b * 256 + t;
    int v = (i < N_NODES) ? g_deg[i] : 0;
    s[t] = v;
    __syncthreads();
    for (int o = 1; o < 256; o <<= 1) {
        int x = (t >= o) ? s[t - o] : 0;
        __syncthreads();
        s[t] += x;
        __syncthreads();
    }
    if (t == 255) {
        g_blockagg[b] = s[255];
        __threadfence();
        is_last = (atomicAdd(&g_aggdone, 1) == NBLK_SCAN - 1);
    }
    __syncthreads();
    if (is_last) {
        int a = (t < NBLK_SCAN) ? ((volatile int*)g_blockagg)[t] : 0;
        ag[t] = a;
        __syncthreads();
        for (int o = 1; o < 256; o <<= 1) {
            int x = (t >= o) ? ag[t - o] : 0;
            __syncthreads();
            ag[t] += x;
            __syncthreads();
        }
        if (t < NBLK_SCAN) g_blockpref[t] = ag[t] - a;   // exclusive
        __threadfence();
        if (t == 0) atomicExch(&g_prefflag, 1);
    }
    if (t == 0) {
        while (((volatile int*)&g_prefflag)[0] == 0) { }
    }
    __syncthreads();
    int pref = ((volatile int*)g_blockpref)[b];
    if (i < N_NODES) {
        int off = pref + s[t] - v;
        g_off[i] = off;
        g_cursor[i] = off;
    }
    __threadfence();
    if (t == 0) {
        atomicAdd(&g_aggdone, 1);                       // counts 196..392
        while (((volatile int*)&g_aggdone)[0] < 2 * NBLK_SCAN) { }
    }
    __syncthreads();
    int base4 = b * EDGES_PER_BLK;
    for (int j = t; j < EDGES_PER_BLK; j += 256) {
        int e4 = (base4 + j) * 4;
        if (e4 + 3 < N_EDGES) {
            uint4 sv = *(const uint4*)(edge + e4);
            uint4 dv = *(const uint4*)(edge + N_EDGES + e4);
            if (dv.x < N_NODES && sv.x < N_NODES) g_srcs[atomicAdd(&g_cursor[dv.x], 1)] = (int)sv.x;
            if (dv.y < N_NODES && sv.y < N_NODES) g_srcs[atomicAdd(&g_cursor[dv.y], 1)] = (int)sv.y;
            if (dv.z < N_NODES && sv.z < N_NODES) g_srcs[atomicAdd(&g_cursor[dv.z], 1)] = (int)sv.z;
            if (dv.w < N_NODES && sv.w < N_NODES) g_srcs[atomicAdd(&g_cursor[dv.w], 1)] = (int)sv.w;
        } else if (e4 < N_EDGES) {
            for (int e = e4; e < N_EDGES; e++) {
                unsigned src = (unsigned)edge[e];
                unsigned dst = (unsigned)edge[N_EDGES + e];
                if (dst < N_NODES && src < N_NODES)
                    g_srcs[atomicAdd(&g_cursor[dst], 1)] = (int)src;
            }
        }
    }
}

// ---------------- aggregation: warp/node, int16 gathers (half L2 bytes) ---------
__global__ void k_agg(const short* __restrict__ inq, const float* __restrict__ ins) {
    int node = (blockIdx.x * blockDim.x + threadIdx.x) >> 5;
    if (node >= N_NODES) return;
    int lane = threadIdx.x & 31;
    int d = g_deg[node];
    int o = g_off[node];
    float a0 = 0.f, a1 = 0.f, a2 = 0.f, a3 = 0.f;
    int e = 0;
    for (; e + 2 <= d; e += 2) {
        int s0 = g_srcs[o + e];
        int s1 = g_srcs[o + e + 1];
        float c0 = ins[s0], c1 = ins[s1];
        uint2 p0 = ((const uint2*)(inq + (size_t)s0 * F))[lane];
        uint2 p1 = ((const uint2*)(inq + (size_t)s1 * F))[lane];
        short2 u0 = *(short2*)&p0.x, u1 = *(short2*)&p0.y;
        short2 w0 = *(short2*)&p1.x, w1 = *(short2*)&p1.y;
        a0 += (float)u0.x * c0 + (float)w0.x * c1;
        a1 += (float)u0.y * c0 + (float)w0.y * c1;
        a2 += (float)u1.x * c0 + (float)w1.x * c1;
        a3 += (float)u1.y * c0 + (float)w1.y * c1;
    }
    if (e < d) {
        int s = g_srcs[o + e];
        float c = ins[s];
        uint2 p = ((const uint2*)(inq + (size_t)s * F))[lane];
        short2 u0 = *(short2*)&p.x, u1 = *(short2*)&p.y;
        a0 += (float)u0.x * c; a1 += (float)u0.y * c;
        a2 += (float)u1.x * c; a3 += (float)u1.y * c;
    }
    float inv = (d > 0) ? 1.0f / (float)d : 0.0f;
    a0 *= inv; a1 *= inv; a2 *= inv; a3 *= inv;
    float m = fmaxf(fmaxf(fabsf(a0), fabsf(a1)), fmaxf(fabsf(a2), fabsf(a3)));
#pragma unroll
    for (int o2 = 16; o2 > 0; o2 >>= 1) m = fmaxf(m, __shfl_xor_sync(0xFFFFFFFFu, m, o2));
    float qs = (m > 0.f) ? 32766.f / m : 0.f;
    int q0 = __float2int_rn(a0 * qs), q1 = __float2int_rn(a1 * qs);
    int q2 = __float2int_rn(a2 * qs), q3 = __float2int_rn(a3 * qs);
    uint2 outp;
    outp.x = (q0 & 0xFFFF) | (q1 << 16);
    outp.y = (q2 & 0xFFFF) | (q3 << 16);
    ((uint2*)(g_mq + (size_t)node * F))[lane] = outp;
    if (lane == 0) g_sm[node] = m / 32766.f;
}

// ---------------- HMMA GEMM: 2 CTAs/SM, int16 A + smem-staged scales ------------
#define SM_BIAS  0                           // 512 B
#define SM_RMAX  512                         // 512 B
#define SM_SCL   1024                        // 512 B
#define SM_AHI   2048
#define SM_ALO   (SM_AHI + 16384)
#define SM_WHI0  (SM_ALO + 16384)
#define SM_WLO0  (SM_WHI0 + 16384)
#define SM_WHI1  (SM_WLO0 + 16384)
#define SM_WLO1  (SM_WHI1 + 16384)
#define SM_TOTAL (SM_WLO1 + 16384)           // 100352 B -> 2 CTAs/SM

__device__ __forceinline__ unsigned swoff(int row, int k) {
    return (unsigned)(row * 128 + ((((k >> 3) ^ row) & 7) << 4) + (k & 7) * 2);
}

__device__ __forceinline__ void issue_w(int chunk, unsigned sb, int tid,
                                        const __nv_bfloat16* Whi,
                                        const __nv_bfloat16* Wlo) {
    int kcW = chunk * 64;
    int buf = chunk & 1;
    unsigned whb = sb + (buf ? SM_WHI1 : SM_WHI0);
    unsigned wlb = sb + (buf ? SM_WLO1 : SM_WLO0);
#pragma unroll
    for (int q = 0; q < 4; q++) {
        int i = tid + q * 256;
        int n = i >> 3;
        int k8 = (i & 7) * 8;
        unsigned off = swoff(n, k8);
        cp16(whb + off, Whi + n * 256 + kcW + k8);
        cp16(wlb + off, Wlo + n * 256 + kcW + k8);
    }
}

__global__ void __launch_bounds__(256, 2) k_gemm(
    const short* __restrict__ Amq, const float* __restrict__ Ams,
    const short* __restrict__ Ahq, const float* __restrict__ Ahs,
    const __nv_bfloat16* __restrict__ Whi,
    const __nv_bfloat16* __restrict__ Wlo,
    const float* __restrict__ bl,
    short* __restrict__ outq, float* __restrict__ outs)
{
    extern __shared__ __align__(16) char smem[];
    unsigned sb = smem_u32(smem);
    int tid = threadIdx.x;
    int wid = tid >> 5;
    int lane = tid & 31;
    int wm = wid & 1;
    int wn = wid >> 1;
    int m0 = blockIdx.x * 128;

    if (tid < 128) {
        *(float*)(smem + SM_BIAS + tid * 4) = bl[tid];
        *(int*)(smem + SM_RMAX + tid * 4) = 0;
    }

    float acc[4][4][4];
#pragma unroll
    for (int a = 0; a < 4; a++)
#pragma unroll
        for (int b = 0; b < 4; b++)
#pragma unroll
            for (int c = 0; c < 4; c++) acc[a][b][c] = 0.f;

    issue_w(0, sb, tid, Whi, Wlo);
    CP_COMMIT();

    for (int chunk = 0; chunk < 4; chunk++) {
        int buf = chunk & 1;
        const short* aq = (chunk < 2) ? Amq : Ahq;
        const float* as = (chunk < 2) ? Ams : Ahs;
        int kcA = (chunk & 1) * 64;

        // A int16 loads + this CTA's row scale (latency hidden by co-resident CTA)
        uint2 av[8];
#pragma unroll
        for (int q = 0; q < 8; q++) {
            int i = tid + q * 256;
            int row = i >> 4;
            int k4 = (i & 15) * 4;
            int gr = m0 + row;
            av[q] = (gr < N_NODES) ? *(const uint2*)(aq + (size_t)gr * F + kcA + k4)
                                   : make_uint2(0, 0);
        }
        float myscale = 0.f;
        if (tid < 128 && m0 + tid < N_NODES) myscale = as[m0 + tid];

        CP_WAIT0();             // W chunk landed
        __syncthreads();        // prev MMA done
        if (chunk < 3) {
            issue_w(chunk + 1, sb, tid, Whi, Wlo);
            CP_COMMIT();
        }
        if (tid < 128) *(float*)(smem + SM_SCL + tid * 4) = myscale;
        __syncthreads();        // scales visible

        // dequant + split -> hi/lo planes
        const float* ssc = (const float*)(smem + SM_SCL);
#pragma unroll
        for (int q = 0; q < 8; q++) {
            int i = tid + q * 256;
            int row = i >> 4;
            int k4 = (i & 15) * 4;
            float sc = ssc[row];
            short2 s01 = *(short2*)&av[q].x;
            short2 s23 = *(short2*)&av[q].y;
            float f0 = (float)s01.x * sc, f1 = (float)s01.y * sc;
            float f2 = (float)s23.x * sc, f3 = (float)s23.y * sc;
            uint2 h, l;
            split2(f0, f1, h.x, l.x);
            split2(f2, f3, h.y, l.y);
            unsigned off = swoff(row, k4);
            *(uint2*)(smem + SM_AHI + off) = h;
            *(uint2*)(smem + SM_ALO + off) = l;
        }
        __syncthreads();

        unsigned whb = sb + (buf ? SM_WHI1 : SM_WHI0);
        unsigned wlb = sb + (buf ? SM_WLO1 : SM_WLO0);
#pragma unroll
        for (int ks = 0; ks < 4; ks++) {
            int kl = ks * 16;
            unsigned bhi[8], blo[8];
            int nrl = (lane >> 4) * 8 + (lane & 7);
            int kkB = kl + ((lane >> 3) & 1) * 8;
#pragma unroll
            for (int nf2 = 0; nf2 < 2; nf2++) {
                int nrow = wn * 32 + nf2 * 16 + nrl;
                unsigned offB = (unsigned)(nrow * 128 + ((((kkB >> 3) ^ nrow) & 7) << 4));
                ldsm_x4(&bhi[nf2 * 4], whb + offB);
                ldsm_x4(&blo[nf2 * 4], wlb + offB);
            }
            int mrl = ((lane >> 3) & 1) * 8 + (lane & 7);
            int kkA = kl + (lane >> 4) * 8;
#pragma unroll
            for (int mf = 0; mf < 4; mf++) {
                unsigned ahi[4], alo[4];
                int mrow = wm * 64 + mf * 16 + mrl;
                unsigned offA = (unsigned)(mrow * 128 + ((((kkA >> 3) ^ mrow) & 7) << 4));
                ldsm_x4(ahi, sb + SM_AHI + offA);
                ldsm_x4(alo, sb + SM_ALO + offA);
#pragma unroll
                for (int nf = 0; nf < 4; nf++) {
                    const unsigned* bh = &bhi[(nf >> 1) * 4 + (nf & 1) * 2];
                    const unsigned* blp = &blo[(nf >> 1) * 4 + (nf & 1) * 2];
                    mma16816(acc[mf][nf], ahi, bh);
                    mma16816(acc[mf][nf], ahi, blp);
                    mma16816(acc[mf][nf], alo, bh);
                }
            }
        }
    }

    // epilogue pass 1: row maxima (post-relu >= 0 -> int-bit atomicMax valid)
    const float* bias = (const float*)(smem + SM_BIAS);
    int* rmax = (int*)(smem + SM_RMAX);
#pragma unroll
    for (int mf = 0; mf < 4; mf++) {
        int la = wm * 64 + mf * 16 + (lane >> 2);
        float mxa = 0.f, mxb = 0.f;
#pragma unroll
        for (int nf = 0; nf < 4; nf++) {
            int col = wn * 32 + nf * 8 + (lane & 3) * 2;
            float b0 = bias[col], b1 = bias[col + 1];
            mxa = fmaxf(mxa, fmaxf(acc[mf][nf][0] + b0, acc[mf][nf][1] + b1));
            mxb = fmaxf(mxb, fmaxf(acc[mf][nf][2] + b0, acc[mf][nf][3] + b1));
        }
        atomicMax(&rmax[la], __float_as_int(fmaxf(mxa, 0.f)));
        atomicMax(&rmax[la + 8], __float_as_int(fmaxf(mxb, 0.f)));
    }
    __syncthreads();
    // epilogue pass 2: quantize + int16 stores (half the store bytes)
#pragma unroll
    for (int mf = 0; mf < 4; mf++) {
        int la = wm * 64 + mf * 16 + (lane >> 2);
        int ra = m0 + la;
        int rb = ra + 8;
        float ma = __int_as_float(rmax[la]);
        float mb = __int_as_float(rmax[la + 8]);
        float qa = (ma > 0.f) ? 32766.f / ma : 0.f;
        float qb = (mb > 0.f) ? 32766.f / mb : 0.f;
        if (wn == 0 && (lane & 3) == 0) {
            if (ra < N_NODES) outs[ra] = ma / 32766.f;
            if (rb < N_NODES) outs[rb] = mb / 32766.f;
        }
#pragma unroll
        for (int nf = 0; nf < 4; nf++) {
            int col = wn * 32 + nf * 8 + (lane & 3) * 2;
            float b0 = bias[col], b1 = bias[col + 1];
            if (ra < N_NODES) {
                float v0 = fmaxf(acc[mf][nf][0] + b0, 0.f);
                float v1 = fmaxf(acc[mf][nf][1] + b1, 0.f);
                int q0 = __float2int_rn(v0 * qa), q1 = __float2int_rn(v1 * qa);
                *(unsigned*)(outq + (size_t)ra * F + col) = (q0 & 0xFFFF) | (q1 << 16);
            }
            if (rb < N_NODES) {
                float v2 = fmaxf(acc[mf][nf][2] + b0, 0.f);
                float v3 = fmaxf(acc[mf][nf][3] + b1, 0.f);
                int q2 = __float2int_rn(v2 * qb), q3 = __float2int_rn(v3 * qb);
                *(unsigned*)(outq + (size_t)rb * F + col) = (q2 & 0xFFFF) | (q3 << 16);
            }
        }
    }
}

// ---------------- final linear (int16 in) + deg re-zero --------------------------
__global__ void k_final(const short* __restrict__ hq, const float* __restrict__ hs,
                        const float* __restrict__ Wf,
                        const float* __restrict__ bf,
                        float* __restrict__ out)
{
    int gid = blockIdx.x * blockDim.x + threadIdx.x;
    if (gid < N_NODES) g_deg[gid] = 0;        // prep for next call's histogram
    int node = gid >> 5;
    if (node >= N_NODES) return;
    int lane = gid & 31;
    float sc = hs[node];
    uint2 p = ((const uint2*)(hq + (size_t)node * F))[lane];
    short2 q0 = *(short2*)&p.x;
    short2 q1 = *(short2*)&p.y;
    float4 wv = ((const float4*)Wf)[lane];
    float s = ((float)q0.x * sc) * wv.x + ((float)q0.y * sc) * wv.y +
              ((float)q1.x * sc) * wv.z + ((float)q1.y * sc) * wv.w;
#pragma unroll
    for (int o = 16; o > 0; o >>= 1) s += __shfl_down_sync(0xFFFFFFFFu, s, o);
    if (lane == 0) out[node] = s + bf[0];
}

// ---------------- launch ------------------------------------------------------------
extern "C" void kernel_launch(void* const* d_in, const int* in_sizes, int n_in,
                              void* d_out, int out_size)
{
    const float* x    = (const float*)d_in[0];
    const int*   edge = (const int*)d_in[1];   // int32 (JAX x64 disabled)
    const float* Wl[3] = {(const float*)d_in[2], (const float*)d_in[5], (const float*)d_in[8]};
    const float* bl[3] = {(const float*)d_in[3], (const float*)d_in[6], (const float*)d_in[9]};
    const float* Wr[3] = {(const float*)d_in[4], (const float*)d_in[7], (const float*)d_in[10]};
    const float* Wf = (const float*)d_in[11];
    const float* bf = (const float*)d_in[12];
    float* out = (float*)d_out;

    cudaFuncSetAttribute(k_gemm, cudaFuncAttributeMaxDynamicSharedMemorySize, SM_TOTAL);

    void* p = nullptr;
    cudaGetSymbolAddress(&p, g_xq);  short* xq = (short*)p;
    cudaGetSymbolAddress(&p, g_hq);  short* h0q = (short*)p;
    short* h1q = h0q + (size_t)N_NODES * F;
    cudaGetSymbolAddress(&p, g_mq);  short* mq = (short*)p;
    cudaGetSymbolAddress(&p, g_sx);  float* sx = (float*)p;
    cudaGetSymbolAddress(&p, g_sh);  float* s0 = (float*)p;
    float* s1 = s0 + N_NODES;
    cudaGetSymbolAddress(&p, g_sm);  float* sm = (float*)p;
    cudaGetSymbolAddress(&p, g_whi); __nv_bfloat16* whi = (__nv_bfloat16*)p;
    cudaGetSymbolAddress(&p, g_wlo); __nv_bfloat16* wlo = (__nv_bfloat16*)p;

    const int AGG_BLOCKS = (N_NODES * 32 + 255) / 256;
    const int GEMM_BLOCKS = (N_NODES + 127) / 128;   // 391

    // 0: prep (pack W + histogram + quantize x + flags)
    k_prep<<<AGG_BLOCKS, 256>>>(x, edge, Wl[0], Wr[0], Wl[1], Wr[1], Wl[2], Wr[2]);
    // 1: fused scan + scatter
    k_scan_scatter<<<NBLK_SCAN, 256>>>(edge);

    // 2: agg0   3: gemm0 (ncu capture slot)
    k_agg<<<AGG_BLOCKS, 256>>>(xq, sx);
    k_gemm<<<GEMM_BLOCKS, 256, SM_TOTAL>>>(mq, sm, xq, sx, whi, wlo, bl[0], h0q, s0);
    // 4,5: layer 1
    k_agg<<<AGG_BLOCKS, 256>>>(h0q, s0);
    k_gemm<<<GEMM_BLOCKS, 256, SM_TOTAL>>>(mq, sm, h0q, s0, whi + 128 * 256, wlo + 128 * 256, bl[1], h1q, s1);
    // 6,7: layer 2
    k_agg<<<AGG_BLOCKS, 256>>>(h1q, s1);
    k_gemm<<<GEMM_BLOCKS, 256, SM_TOTAL>>>(mq, sm, h1q, s1, whi + 2 * 128 * 256, wlo + 2 * 128 * 256, bl[2], h0q, s0);
    // 8: final (+ deg zero for next call)
    k_final<<<AGG_BLOCKS, 256>>>(h0q, s0, Wf, bf, out);
}

// round 17
// speedup vs baseline: 1.1257x; 1.1257x over previous
#include <cuda_runtime.h>
#include <cuda_bf16.h>
#include <cstdint>

#define N_NODES 50000
#define N_EDGES 800000
#define F 128
#define NBLK_SCAN 196        // ceil(50000/256)

// ---------------- scratch (static device memory) -----------------------------
__device__ float g_h[2][(size_t)N_NODES * F];           // fp32 hidden (ping-pong)
__device__ float g_mean[(size_t)N_NODES * F];           // fp32 mean
__device__ __nv_bfloat16 g_whi[3 * 128 * 256];          // combined [Wl|Wr] hi
__device__ __nv_bfloat16 g_wlo[3 * 128 * 256];          // combined [Wl|Wr] lo
__device__ int g_deg[N_NODES];                          // zero-init; re-zeroed by k_final
__device__ int g_off[N_NODES];
__device__ int g_cursor[N_NODES];
__device__ int g_srcs[N_EDGES];
__device__ int g_blockagg[NBLK_SCAN];
__device__ int g_blockpref[NBLK_SCAN];
__device__ int g_aggdone;
__device__ int g_prefflag;

// ---------------- helpers ------------------------------------------------------
__device__ __forceinline__ unsigned smem_u32(const void* p) {
    unsigned a;
    asm("{ .reg .u64 t; cvta.to.shared.u64 t, %1; cvt.u32.u64 %0, t; }" : "=r"(a) : "l"(p));
    return a;
}
__device__ __forceinline__ void ldsm_x4(unsigned* r, unsigned addr) {
    asm volatile("ldmatrix.sync.aligned.m8n8.x4.shared.b16 {%0,%1,%2,%3}, [%4];"
                 : "=r"(r[0]), "=r"(r[1]), "=r"(r[2]), "=r"(r[3]) : "r"(addr));
}
__device__ __forceinline__ void mma16816(float* c, const unsigned* a, const unsigned* b) {
    asm volatile(
        "mma.sync.aligned.m16n8k16.row.col.f32.bf16.bf16.f32 "
        "{%0,%1,%2,%3}, {%4,%5,%6,%7}, {%8,%9}, {%0,%1,%2,%3};"
        : "+f"(c[0]), "+f"(c[1]), "+f"(c[2]), "+f"(c[3])
        : "r"(a[0]), "r"(a[1]), "r"(a[2]), "r"(a[3]), "r"(b[0]), "r"(b[1]));
}
__device__ __forceinline__ void split2(float f0, float f1, unsigned& hw, unsigned& lw) {
    __nv_bfloat162 hb = __floats2bfloat162_rn(f0, f1);
    hw = *(unsigned*)&hb;
    float r0 = f0 - __uint_as_float(hw << 16);
    float r1 = f1 - __uint_as_float(hw & 0xFFFF0000u);
    __nv_bfloat162 lb = __floats2bfloat162_rn(r0, r1);
    lw = *(unsigned*)&lb;
}
__device__ __forceinline__ void cp16(unsigned dst, const void* src) {
    asm volatile("cp.async.cg.shared.global [%0], [%1], 16;" :: "r"(dst), "l"(src));
}
#define CP_COMMIT() asm volatile("cp.async.commit_group;" ::: "memory")
#define CP_WAIT0()  asm volatile("cp.async.wait_group 0;" ::: "memory")

// ---------------- launch 0: prep (pack W + hist + flag reset) --------------------
__global__ void k_prep(const int* __restrict__ edge,
                       const float* Wl0, const float* Wr0,
                       const float* Wl1, const float* Wr1,
                       const float* Wl2, const float* Wr2) {
    int gid = blockIdx.x * blockDim.x + threadIdx.x;
    if (gid == 0) { g_aggdone = 0; g_prefflag = 0; }
    if (gid < N_EDGES / 4) {
        uint4 d = *(const uint4*)(edge + N_EDGES + gid * 4);
        if (d.x < N_NODES) atomicAdd(&g_deg[d.x], 1);
        if (d.y < N_NODES) atomicAdd(&g_deg[d.y], 1);
        if (d.z < N_NODES) atomicAdd(&g_deg[d.z], 1);
        if (d.w < N_NODES) atomicAdd(&g_deg[d.w], 1);
    }
    if (gid < 3 * 128 * 256) {
        int L = gid / (128 * 256);
        int r = gid % (128 * 256);
        int n = r / 256;
        int k = r % 256;
        const float* Wl = (L == 0) ? Wl0 : (L == 1) ? Wl1 : Wl2;
        const float* Wr = (L == 0) ? Wr0 : (L == 1) ? Wr1 : Wr2;
        float v = (k < 128) ? Wl[n * 128 + k] : Wr[n * 128 + (k - 128)];
        __nv_bfloat16 h = __float2bfloat16(v);
        float r2 = v - __bfloat162float(h);
        g_whi[gid] = h;
        g_wlo[gid] = __float2bfloat16(r2);
    }
}

// ---------------- launch 1: fused scan + scatter (grid-resident) ----------------
#define EDGES_PER_BLK 1021    // 196*1021*4 >= 800000 (units of 4 edges)
__global__ void __launch_bounds__(256, 8) k_scan_scatter(const int* __restrict__ edge) {
    __shared__ int s[256];
    __shared__ int ag[256];
    __shared__ int is_last;
    int b = blockIdx.x, t = threadIdx.x;
    int i = b * 256 + t;
    int v = (i < N_NODES) ? g_deg[i] : 0;
    s[t] = v;
    __syncthreads();
    for (int o = 1; o < 256; o <<= 1) {
        int x = (t >= o) ? s[t - o] : 0;
        __syncthreads();
        s[t] += x;
        __syncthreads();
    }
    if (t == 255) {
        g_blockagg[b] = s[255];
        __threadfence();
        is_last = (atomicAdd(&g_aggdone, 1) == NBLK_SCAN - 1);
    }
    __syncthreads();
    if (is_last) {
        int a = (t < NBLK_SCAN) ? ((volatile int*)g_blockagg)[t] : 0;
        ag[t] = a;
        __syncthreads();
        for (int o = 1; o < 256; o <<= 1) {
            int x = (t >= o) ? ag[t - o] : 0;
            __syncthreads();
            ag[t] += x;
            __syncthreads();
        }
        if (t < NBLK_SCAN) g_blockpref[t] = ag[t] - a;   // exclusive
        __threadfence();
        if (t == 0) atomicExch(&g_prefflag, 1);
    }
    if (t == 0) {
        while (((volatile int*)&g_prefflag)[0] == 0) { }
    }
    __syncthreads();
    int pref = ((volatile int*)g_blockpref)[b];
    if (i < N_NODES) {
        int off = pref + s[t] - v;
        g_off[i] = off;
        g_cursor[i] = off;
    }
    __threadfence();
    if (t == 0) {
        atomicAdd(&g_aggdone, 1);                       // counts 196..392
        while (((volatile int*)&g_aggdone)[0] < 2 * NBLK_SCAN) { }
    }
    __syncthreads();
    int base4 = b * EDGES_PER_BLK;
    for (int j = t; j < EDGES_PER_BLK; j += 256) {
        int e4 = (base4 + j) * 4;
        if (e4 + 3 < N_EDGES) {
            uint4 sv = *(const uint4*)(edge + e4);
            uint4 dv = *(const uint4*)(edge + N_EDGES + e4);
            if (dv.x < N_NODES && sv.x < N_NODES) g_srcs[atomicAdd(&g_cursor[dv.x], 1)] = (int)sv.x;
            if (dv.y < N_NODES && sv.y < N_NODES) g_srcs[atomicAdd(&g_cursor[dv.y], 1)] = (int)sv.y;
            if (dv.z < N_NODES && sv.z < N_NODES) g_srcs[atomicAdd(&g_cursor[dv.z], 1)] = (int)sv.z;
            if (dv.w < N_NODES && sv.w < N_NODES) g_srcs[atomicAdd(&g_cursor[dv.w], 1)] = (int)sv.w;
        } else if (e4 < N_EDGES) {
            for (int e = e4; e < N_EDGES; e++) {
                unsigned src = (unsigned)edge[e];
                unsigned dst = (unsigned)edge[N_EDGES + e];
                if (dst < N_NODES && src < N_NODES)
                    g_srcs[atomicAdd(&g_cursor[dst], 1)] = (int)src;
            }
        }
    }
}

// ---------------- aggregation: warp per node, 64-thread blocks ------------------
// 2 warps per block -> block latency = max of 2 node degrees (was max of 8)
__global__ void __launch_bounds__(64, 32) k_agg(const float* __restrict__ in) {
    int node = blockIdx.x * 2 + (threadIdx.x >> 5);
    if (node >= N_NODES) return;
    int lane = threadIdx.x & 31;
    int d = g_deg[node];
    int o = g_off[node];
    float a0 = 0.f, a1 = 0.f, a2 = 0.f, a3 = 0.f;
    for (int e = 0; e < d; e++) {
        int s = g_srcs[o + e];
        float4 v = ((const float4*)(in + (size_t)s * F))[lane];
        a0 += v.x; a1 += v.y; a2 += v.z; a3 += v.w;
    }
    float inv = (d > 0) ? 1.0f / (float)d : 0.0f;
    ((float4*)(g_mean + (size_t)node * F))[lane] =
        make_float4(a0 * inv, a1 * inv, a2 * inv, a3 * inv);
}

// ---------------- HMMA GEMM: 2 CTAs/SM, W cp.async double-buffered (R13 exact) --
#define SM_BIAS  0
#define SM_AHI   1024
#define SM_ALO   (SM_AHI + 16384)
#define SM_WHI0  (SM_ALO + 16384)
#define SM_WLO0  (SM_WHI0 + 16384)
#define SM_WHI1  (SM_WLO0 + 16384)
#define SM_WLO1  (SM_WHI1 + 16384)
#define SM_TOTAL (SM_WLO1 + 16384)   // 99328 bytes -> 2 CTAs/SM

__device__ __forceinline__ unsigned swoff(int row, int k) {
    return (unsigned)(row * 128 + ((((k >> 3) ^ row) & 7) << 4) + (k & 7) * 2);
}

__device__ __forceinline__ void issue_w(int chunk, unsigned sb, int tid,
                                        const __nv_bfloat16* Whi,
                                        const __nv_bfloat16* Wlo) {
    int kcW = chunk * 64;
    int buf = chunk & 1;
    unsigned whb = sb + (buf ? SM_WHI1 : SM_WHI0);
    unsigned wlb = sb + (buf ? SM_WLO1 : SM_WLO0);
#pragma unroll
    for (int q = 0; q < 4; q++) {
        int i = tid + q * 256;             // 0..1023
        int n = i >> 3;
        int k8 = (i & 7) * 8;
        unsigned off = swoff(n, k8);
        cp16(whb + off, Whi + n * 256 + kcW + k8);
        cp16(wlb + off, Wlo + n * 256 + kcW + k8);
    }
}

__global__ void __launch_bounds__(256, 2) k_gemm(
    const float* __restrict__ Am,
    const float* __restrict__ Ah,
    const __nv_bfloat16* __restrict__ Whi,
    const __nv_bfloat16* __restrict__ Wlo,
    const float* __restrict__ bl,
    float* __restrict__ outh)
{
    extern __shared__ __align__(16) char smem[];
    unsigned sb = smem_u32(smem);
    int tid = threadIdx.x;
    int wid = tid >> 5;
    int lane = tid & 31;
    int wm = wid & 1;
    int wn = wid >> 1;
    int m0 = blockIdx.x * 128;

    if (tid < 128) *(float*)(smem + SM_BIAS + tid * 4) = bl[tid];

    float acc[4][4][4];
#pragma unroll
    for (int a = 0; a < 4; a++)
#pragma unroll
        for (int b = 0; b < 4; b++)
#pragma unroll
            for (int c = 0; c < 4; c++) acc[a][b][c] = 0.f;

    issue_w(0, sb, tid, Whi, Wlo);
    CP_COMMIT();

    for (int chunk = 0; chunk < 4; chunk++) {
        int buf = chunk & 1;
        const float* ap = (chunk < 2) ? Am : Ah;
        int kcA = (chunk & 1) * 64;

        // A: direct LDG into regs (latency overlapped by co-resident CTA)
        float4 av[8];
#pragma unroll
        for (int q = 0; q < 8; q++) {
            int i = tid + q * 256;
            int row = i >> 4;
            int k4 = (i & 15) * 4;
            int gr = m0 + row;
            av[q] = (gr < N_NODES) ? *(const float4*)(ap + (size_t)gr * F + kcA + k4)
                                   : make_float4(0.f, 0.f, 0.f, 0.f);
        }

        CP_WAIT0();             // W chunk landed
        __syncthreads();        // prev MMA done; A planes free
        if (chunk < 3) {
            issue_w(chunk + 1, sb, tid, Whi, Wlo);
            CP_COMMIT();
        }
        // split A regs -> hi/lo planes
#pragma unroll
        for (int q = 0; q < 8; q++) {
            int i = tid + q * 256;
            int row = i >> 4;
            int k4 = (i & 15) * 4;
            uint2 h, l;
            split2(av[q].x, av[q].y, h.x, l.x);
            split2(av[q].z, av[q].w, h.y, l.y);
            unsigned off = swoff(row, k4);
            *(uint2*)(smem + SM_AHI + off) = h;
            *(uint2*)(smem + SM_ALO + off) = l;
        }
        __syncthreads();

        unsigned whb = sb + (buf ? SM_WHI1 : SM_WHI0);
        unsigned wlb = sb + (buf ? SM_WLO1 : SM_WLO0);
#pragma unroll
        for (int ks = 0; ks < 4; ks++) {
            int kl = ks * 16;
            unsigned bhi[8], blo[8];
            int nrl = (lane >> 4) * 8 + (lane & 7);
            int kkB = kl + ((lane >> 3) & 1) * 8;
#pragma unroll
            for (int nf2 = 0; nf2 < 2; nf2++) {
                int nrow = wn * 32 + nf2 * 16 + nrl;
                unsigned offB = (unsigned)(nrow * 128 + ((((kkB >> 3) ^ nrow) & 7) << 4));
                ldsm_x4(&bhi[nf2 * 4], whb + offB);
                ldsm_x4(&blo[nf2 * 4], wlb + offB);
            }
            int mrl = ((lane >> 3) & 1) * 8 + (lane & 7);
            int kkA = kl + (lane >> 4) * 8;
#pragma unroll
            for (int mf = 0; mf < 4; mf++) {
                unsigned ahi[4], alo[4];
                int mrow = wm * 64 + mf * 16 + mrl;
                unsigned offA = (unsigned)(mrow * 128 + ((((kkA >> 3) ^ mrow) & 7) << 4));
                ldsm_x4(ahi, sb + SM_AHI + offA);
                ldsm_x4(alo, sb + SM_ALO + offA);
#pragma unroll
                for (int nf = 0; nf < 4; nf++) {
                    const unsigned* bh = &bhi[(nf >> 1) * 4 + (nf & 1) * 2];
                    const unsigned* blp = &blo[(nf >> 1) * 4 + (nf & 1) * 2];
                    mma16816(acc[mf][nf], ahi, bh);
                    mma16816(acc[mf][nf], ahi, blp);
                    mma16816(acc[mf][nf], alo, bh);
                }
            }
        }
    }

    // epilogue: bias + relu, fp32 stores
    const float* bias = (const float*)(smem + SM_BIAS);
#pragma unroll
    for (int mf = 0; mf < 4; mf++) {
        int ra = m0 + wm * 64 + mf * 16 + (lane >> 2);
        int rb = ra + 8;
#pragma unroll
        for (int nf = 0; nf < 4; nf++) {
            int col = wn * 32 + nf * 8 + (lane & 3) * 2;
            float b0 = bias[col], b1 = bias[col + 1];
            if (ra < N_NODES) {
                float v0 = fmaxf(acc[mf][nf][0] + b0, 0.f);
                float v1 = fmaxf(acc[mf][nf][1] + b1, 0.f);
                *(float2*)(outh + (size_t)ra * F + col) = make_float2(v0, v1);
            }
            if (rb < N_NODES) {
                float v2 = fmaxf(acc[mf][nf][2] + b0, 0.f);
                float v3 = fmaxf(acc[mf][nf][3] + b1, 0.f);
                *(float2*)(outh + (size_t)rb * F + col) = make_float2(v2, v3);
            }
        }
    }
}

// ---------------- final linear + deg re-zero for next call ----------------------
__global__ void k_final(const float* __restrict__ h,
                        const float* __restrict__ Wf,
                        const float* __restrict__ bf,
                        float* __restrict__ out)
{
    int gid = blockIdx.x * blockDim.x + threadIdx.x;
    if (gid < N_NODES) g_deg[gid] = 0;        // prep for next call's histogram
    int node = gid >> 5;
    if (node >= N_NODES) return;
    int lane = gid & 31;
    float4 hv = ((const float4*)(h + (size_t)node * F))[lane];
    float4 wv = ((const float4*)Wf)[lane];
    float s = hv.x * wv.x + hv.y * wv.y + hv.z * wv.z + hv.w * wv.w;
#pragma unroll
    for (int o = 16; o > 0; o >>= 1) s += __shfl_down_sync(0xFFFFFFFFu, s, o);
    if (lane == 0) out[node] = s + bf[0];
}

// ---------------- launch ------------------------------------------------------------
extern "C" void kernel_launch(void* const* d_in, const int* in_sizes, int n_in,
                              void* d_out, int out_size)
{
    const float* x    = (const float*)d_in[0];
    const int*   edge = (const int*)d_in[1];   // int32 (JAX x64 disabled)
    const float* Wl[3] = {(const float*)d_in[2], (const float*)d_in[5], (const float*)d_in[8]};
    const float* bl[3] = {(const float*)d_in[3], (const float*)d_in[6], (const float*)d_in[9]};
    const float* Wr[3] = {(const float*)d_in[4], (const float*)d_in[7], (const float*)d_in[10]};
    const float* Wf = (const float*)d_in[11];
    const float* bf = (const float*)d_in[12];
    float* out = (float*)d_out;

    cudaFuncSetAttribute(k_gemm, cudaFuncAttributeMaxDynamicSharedMemorySize, SM_TOTAL);

    void* p = nullptr;
    cudaGetSymbolAddress(&p, g_h);
    float* h0 = (float*)p;
    float* h1 = h0 + (size_t)N_NODES * F;
    cudaGetSymbolAddress(&p, g_mean);
    float* mp = (float*)p;
    cudaGetSymbolAddress(&p, g_whi);
    __nv_bfloat16* whi = (__nv_bfloat16*)p;
    cudaGetSymbolAddress(&p, g_wlo);
    __nv_bfloat16* wlo = (__nv_bfloat16*)p;

    const int AGG_BLOCKS = (N_NODES + 1) / 2;          // 64-thread blocks, 2 nodes each
    const int FIN_BLOCKS = (N_NODES * 32 + 255) / 256;
    const int GEMM_BLOCKS = (N_NODES + 127) / 128;     // 391

    // 0: prep (pack W + histogram + flag reset)
    k_prep<<<(N_EDGES / 4 + 255) / 256, 256>>>(edge, Wl[0], Wr[0], Wl[1], Wr[1], Wl[2], Wr[2]);
    // 1: fused scan + scatter
    k_scan_scatter<<<NBLK_SCAN, 256>>>(edge);

    // 2: agg0   3: gemm0 (ncu capture slot)
    k_agg<<<AGG_BLOCKS, 64>>>(x);
    k_gemm<<<GEMM_BLOCKS, 256, SM_TOTAL>>>(mp, x, whi, wlo, bl[0], h0);
    // 4,5: layer 1
    k_agg<<<AGG_BLOCKS, 64>>>(h0);
    k_gemm<<<GEMM_BLOCKS, 256, SM_TOTAL>>>(mp, h0, whi + 128 * 256, wlo + 128 * 256, bl[1], h1);
    // 6,7: layer 2
    k_agg<<<AGG_BLOCKS, 64>>>(h1);
    k_gemm<<<GEMM_BLOCKS, 256, SM_TOTAL>>>(mp, h1, whi + 2 * 128 * 256, wlo + 2 * 128 * 256, bl[2], h0);
    // 8: final (+ deg zero for next call)
    k_final<<<FIN_BLOCKS, 256>>>(h0, Wf, bf, out);
}